// round 1
// baseline (speedup 1.0000x reference)
#include <cuda_runtime.h>
#include <cstdint>
#include <cstddef>

// ---------------- problem dims ----------------
#define kB   8
#define kSP  1024
#define kSF  1024
#define kS   2048
#define kXD  6
#define kD   512
#define kL   4
#define kH   8
#define kW   128
#define kDH  64
#define kC   16
#define kFF  2048
#define kM   (kB * kS)          // 16384 rows

// ---------------- scratch (__device__ globals; no runtime alloc) ----------------
__device__ float g_h   [(size_t)kB * kS * kD];
__device__ float g_ln  [(size_t)kB * kS * kD];
__device__ float g_q   [(size_t)kB * kS * kD];
__device__ float g_k   [(size_t)kB * kS * kD];
__device__ float g_v   [(size_t)kB * kS * kD];
__device__ float g_attn[(size_t)kB * kS * kD];
__device__ float g_ffn [(size_t)kB * kS * kFF];
__device__ float g_scores[(size_t)kB * kH * kC * kS];
__device__ float g_cnt [(size_t)kB * kH * kS];
__device__ int   g_iq  [(size_t)kB * kH * kC * kW];
__device__ int   g_ik  [(size_t)kB * kH * kC * kW];

// ---------------- helpers ----------------
__device__ __forceinline__ float gelu_tanh(float x) {
    // jax.nn.gelu default (approximate=True)
    float x3 = x * x * x;
    return 0.5f * x * (1.0f + tanhf(0.7978845608028654f * (x + 0.044715f * x3)));
}

// ---------------- embedding: build x=(ctx|tgt) and h = x@W_emb + b_emb ----------------
__global__ void embed_kernel(const float* __restrict__ past_x,
                             const float* __restrict__ past_y,
                             const float* __restrict__ future_x,
                             const float* __restrict__ W_emb,
                             const float* __restrict__ b_emb,
                             float* __restrict__ h) {
    int idx = blockIdx.x * blockDim.x + threadIdx.x;
    if (idx >= kB * kS * kD) return;
    int d = idx % kD;
    int s = (idx / kD) % kS;
    int b = idx / (kD * kS);
    float feat[kXD + 1];
    if (s < kSP) {
#pragma unroll
        for (int j = 0; j < kXD; j++) feat[j] = past_x[((size_t)b * kSP + s) * kXD + j];
        feat[kXD] = past_y[(size_t)b * kSP + s];
    } else {
        int sf = s - kSP;
#pragma unroll
        for (int j = 0; j < kXD; j++) feat[j] = future_x[((size_t)b * kSF + sf) * kXD + j];
        feat[kXD] = past_y[(size_t)b * kSP + (kSP - 1)];   // repeat last observed y
    }
    float acc = b_emb[d];
#pragma unroll
    for (int j = 0; j < kXD + 1; j++) acc += feat[j] * W_emb[(size_t)j * kD + d];
    h[idx] = acc;
}

// ---------------- layernorm over last dim (D=512), block per row, 128 threads ----------------
__global__ void ln_kernel(const float* __restrict__ x, float* __restrict__ y,
                          const float* __restrict__ g, const float* __restrict__ bb) {
    __shared__ float red[8];
    int row = blockIdx.x;
    int t = threadIdx.x;  // 0..127, each handles 4 consecutive floats
    const float4 xv = ((const float4*)(x + (size_t)row * kD))[t];
    float s = xv.x + xv.y + xv.z + xv.w;
#pragma unroll
    for (int o = 16; o; o >>= 1) s += __shfl_xor_sync(0xffffffffu, s, o);
    if ((t & 31) == 0) red[t >> 5] = s;
    __syncthreads();
    float mean = (red[0] + red[1] + red[2] + red[3]) * (1.0f / kD);
    float dx = xv.x - mean, dy = xv.y - mean, dz = xv.z - mean, dw = xv.w - mean;
    float s2 = dx * dx + dy * dy + dz * dz + dw * dw;
#pragma unroll
    for (int o = 16; o; o >>= 1) s2 += __shfl_xor_sync(0xffffffffu, s2, o);
    if ((t & 31) == 0) red[4 + (t >> 5)] = s2;
    __syncthreads();
    float var = (red[4] + red[5] + red[6] + red[7]) * (1.0f / kD);
    float rstd = rsqrtf(var + 1e-5f);
    const float4 gg = ((const float4*)g)[t];
    const float4 bv = ((const float4*)bb)[t];
    float4 o4;
    o4.x = dx * rstd * gg.x + bv.x;
    o4.y = dy * rstd * gg.y + bv.y;
    o4.z = dz * rstd * gg.z + bv.z;
    o4.w = dw * rstd * gg.w + bv.w;
    ((float4*)(y + (size_t)row * kD))[t] = o4;
}

// ---------------- SGEMM: C = act(A@B + bias + res), M%128==0, N%128==0, K%8==0 ----------------
#define TBM 128
#define TBN 128
#define TBK 8
__global__ __launch_bounds__(256) void sgemm_kernel(
    const float* __restrict__ A, const float* __restrict__ Bm,
    const float* __restrict__ bias, const float* __restrict__ res,
    float* __restrict__ Cm, int M, int N, int K, int act) {
    __shared__ float As[TBK][TBM];
    __shared__ float Bs[TBK][TBN];
    int tid = threadIdx.x;
    int bx = blockIdx.x, by = blockIdx.y;
    int tx = tid % 16, ty = tid / 16;
    const float* Ab = A + (size_t)by * TBM * K;
    const float* Bb = Bm + (size_t)bx * TBN;
    float acc[8][8];
#pragma unroll
    for (int i = 0; i < 8; i++)
#pragma unroll
        for (int j = 0; j < 8; j++) acc[i][j] = 0.f;

    int aRow = tid >> 1, aCol = (tid & 1) * 4;
    int bRow = tid >> 5, bCol = (tid & 31) * 4;

    for (int k0 = 0; k0 < K; k0 += TBK) {
        float4 av = *(const float4*)(Ab + (size_t)aRow * K + k0 + aCol);
        As[aCol + 0][aRow] = av.x;
        As[aCol + 1][aRow] = av.y;
        As[aCol + 2][aRow] = av.z;
        As[aCol + 3][aRow] = av.w;
        *(float4*)(&Bs[bRow][bCol]) = *(const float4*)(Bb + (size_t)(k0 + bRow) * N + bCol);
        __syncthreads();
#pragma unroll
        for (int k = 0; k < TBK; k++) {
            float ar[8], br[8];
#pragma unroll
            for (int i = 0; i < 8; i += 4) *(float4*)(ar + i) = *(const float4*)(&As[k][ty * 8 + i]);
#pragma unroll
            for (int j = 0; j < 8; j += 4) *(float4*)(br + j) = *(const float4*)(&Bs[k][tx * 8 + j]);
#pragma unroll
            for (int i = 0; i < 8; i++)
#pragma unroll
                for (int j = 0; j < 8; j++) acc[i][j] += ar[i] * br[j];
        }
        __syncthreads();
    }
#pragma unroll
    for (int i = 0; i < 8; i++) {
        int row = by * TBM + ty * 8 + i;
        int col0 = bx * TBN + tx * 8;
        float* crow = Cm + (size_t)row * N + col0;
        const float* rrow = res ? res + (size_t)row * N + col0 : nullptr;
#pragma unroll
        for (int j = 0; j < 8; j++) {
            float v = acc[i][j];
            if (bias) v += bias[col0 + j];
            if (rrow) v += rrow[j];
            if (act) v = gelu_tanh(v);
            crow[j] = v;
        }
    }
}

// ---------------- routing scores: scores[b,h,c,s] = normalize(q[b,h,s])·means[h,c] ----------------
__global__ void score_kernel(const float* __restrict__ qk,
                             const float* __restrict__ means,   // (H,C,DH) for this layer
                             float* __restrict__ scores) {
    int bs = blockIdx.x;                 // b*S + s
    int b = bs / kS, s = bs % kS;
    int h = threadIdx.x >> 5, lane = threadIdx.x & 31;   // 8 warps = 8 heads
    const float* qrow = qk + (size_t)bs * kD + h * kDH;
    float qa = qrow[lane], qb = qrow[lane + 32];
    float nrm = qa * qa + qb * qb;
#pragma unroll
    for (int o = 16; o; o >>= 1) nrm += __shfl_xor_sync(0xffffffffu, nrm, o);
    float rn = rsqrtf(nrm + 1e-8f);
#pragma unroll
    for (int c = 0; c < kC; c++) {
        const float* mrow = means + ((size_t)h * kC + c) * kDH;
        float p = qa * mrow[lane] + qb * mrow[lane + 32];
#pragma unroll
        for (int o = 16; o; o >>= 1) p += __shfl_xor_sync(0xffffffffu, p, o);
        if (lane == 0)
            scores[(((size_t)b * kH + h) * kC + c) * kS + s] = p * rn;
    }
}

// ---------------- top-W of S via full bitonic sort (set semantics suffice) ----------------
__global__ void topk_kernel(const float* __restrict__ scores, int* __restrict__ idxout) {
    __shared__ unsigned long long keys[kS];
    int blk = blockIdx.x;                                // (b*H+h)*C + c
    const float* sp = scores + (size_t)blk * kS;
    for (int i = threadIdx.x; i < kS; i += blockDim.x) {
        unsigned u = __float_as_uint(sp[i]);
        u = (u & 0x80000000u) ? ~u : (u | 0x80000000u);  // order-preserving flip
        keys[i] = ((unsigned long long)u << 32) | (unsigned)i;
    }
    __syncthreads();
    for (int k = 2; k <= kS; k <<= 1) {
        for (int j = k >> 1; j > 0; j >>= 1) {
            for (int i = threadIdx.x; i < kS; i += blockDim.x) {
                int ixj = i ^ j;
                if (ixj > i) {
                    unsigned long long a = keys[i], b = keys[ixj];
                    bool up = ((i & k) == 0);            // descending overall
                    bool sw = up ? (a < b) : (a > b);
                    if (sw) { keys[i] = b; keys[ixj] = a; }
                }
            }
            __syncthreads();
        }
    }
    if (threadIdx.x < kW)
        idxout[(size_t)blk * kW + threadIdx.x] = (int)(keys[threadIdx.x] & 0xffffffffu);
}

// ---------------- within-cluster attention + scatter-add ----------------
__global__ __launch_bounds__(128) void attn_kernel(
    const float* __restrict__ q, const float* __restrict__ k, const float* __restrict__ v,
    const int* __restrict__ iq, const int* __restrict__ ik,
    float* __restrict__ attnout, float* __restrict__ cnt) {
    int blk = blockIdx.x;                 // (b*H+h)*C + c
    int h = (blk / kC) % kH;
    int b = blk / (kC * kH);
    extern __shared__ float smem[];
    float* ks = smem;                     // [W][DH]
    float* vs = smem + kW * kDH;          // [W][DH]
    int t = threadIdx.x;                  // 0..127 = query slot within cluster
    const int* ikp = ik + (size_t)blk * kW;
    const int* iqp = iq + (size_t)blk * kW;
    {
        int sk = ikp[t];
        const float4* krow = (const float4*)(k + ((size_t)b * kS + sk) * kD + h * kDH);
        const float4* vrow = (const float4*)(v + ((size_t)b * kS + sk) * kD + h * kDH);
        float4* ksr = (float4*)(ks + (size_t)t * kDH);
        float4* vsr = (float4*)(vs + (size_t)t * kDH);
#pragma unroll
        for (int i = 0; i < kDH / 4; i++) { ksr[i] = krow[i]; vsr[i] = vrow[i]; }
    }
    __syncthreads();
    int sq = iqp[t];
    float qreg[kDH];
    {
        const float4* qrow = (const float4*)(q + ((size_t)b * kS + sq) * kD + h * kDH);
#pragma unroll
        for (int i = 0; i < kDH / 4; i++) ((float4*)qreg)[i] = qrow[i];
    }
    float m = -1e30f, l = 0.f;
    float accv[kDH];
#pragma unroll
    for (int d = 0; d < kDH; d++) accv[d] = 0.f;
    const float scale = 0.125f;           // DH^-0.5

    for (int j = 0; j < kW; j++) {
        const float* kj = ks + (size_t)j * kDH;
        float s0 = 0, s1 = 0, s2 = 0, s3 = 0;
#pragma unroll
        for (int d = 0; d < kDH; d += 4) {
            s0 += qreg[d + 0] * kj[d + 0];
            s1 += qreg[d + 1] * kj[d + 1];
            s2 += qreg[d + 2] * kj[d + 2];
            s3 += qreg[d + 3] * kj[d + 3];
        }
        float s = (s0 + s1 + s2 + s3) * scale;
        float mn = fmaxf(m, s);
        float corr = __expf(m - mn);
        float p = __expf(s - mn);
        l = l * corr + p;
        const float* vj = vs + (size_t)j * kDH;
#pragma unroll
        for (int d = 0; d < kDH; d++) accv[d] = accv[d] * corr + p * vj[d];
        m = mn;
    }
    float inv = 1.0f / l;
    float* orow = attnout + ((size_t)b * kS + sq) * kD + h * kDH;
#pragma unroll
    for (int d = 0; d < kDH; d++) atomicAdd(orow + d, accv[d] * inv);
    atomicAdd(cnt + ((size_t)b * kH + h) * kS + sq, 1.0f);
}

// ---------------- scatter-mean divide ----------------
__global__ void divcnt_kernel(float* __restrict__ attn, const float* __restrict__ cnt) {
    int idx = blockIdx.x * blockDim.x + threadIdx.x;
    if (idx >= kB * kS * kD) return;
    int d = idx % kD;
    int h = d >> 6;                        // d / DH
    int s = (idx / kD) % kS;
    int b = idx / (kD * kS);
    float c = cnt[((size_t)b * kH + h) * kS + s];
    attn[idx] = attn[idx] / fmaxf(c, 1.0f);
}

// ---------------- output heads ----------------
__global__ void head_kernel(const float* __restrict__ hln,
                            const float* __restrict__ Wm, const float* __restrict__ bm,
                            const float* __restrict__ Ws, const float* __restrict__ bsd,
                            float* __restrict__ out) {
    int warp = (blockIdx.x * blockDim.x + threadIdx.x) >> 5;
    int lane = threadIdx.x & 31;
    if (warp >= kB * kSF) return;
    int b = warp / kSF, sf = warp % kSF;
    const float* row = hln + ((size_t)b * kS + kSP + sf) * kD;
    float mdot = 0.f, sdot = 0.f;
    for (int d = lane; d < kD; d += 32) {
        float x = row[d];
        mdot += x * Wm[d];
        sdot += x * Ws[d];
    }
#pragma unroll
    for (int o = 16; o; o >>= 1) {
        mdot += __shfl_xor_sync(0xffffffffu, mdot, o);
        sdot += __shfl_xor_sync(0xffffffffu, sdot, o);
    }
    if (lane == 0) {
        out[warp] = mdot + bm[0];
        float ls = sdot + bsd[0];
        float sp = fmaxf(ls, 0.f) + log1pf(__expf(-fabsf(ls)));  // stable softplus
        out[(size_t)kB * kSF + warp] = 0.01f + 0.99f * sp;
    }
}

// ---------------- host orchestration ----------------
static void launch_gemm(const float* A, const float* Bm, const float* bias,
                        const float* res, float* C, int M, int N, int K, int act) {
    dim3 grid(N / TBN, M / TBM);
    sgemm_kernel<<<grid, 256>>>(A, Bm, bias, res, C, M, N, K, act);
}

extern "C" void kernel_launch(void* const* d_in, const int* in_sizes, int n_in,
                              void* d_out, int out_size) {
    const float* past_x   = (const float*)d_in[0];
    const float* past_y   = (const float*)d_in[1];
    const float* future_x = (const float*)d_in[2];
    const float* W_emb    = (const float*)d_in[3];
    const float* b_emb    = (const float*)d_in[4];
    const float* ln1_g    = (const float*)d_in[5];
    const float* ln1_b    = (const float*)d_in[6];
    const float* Wq       = (const float*)d_in[7];
    const float* Wk       = (const float*)d_in[8];
    const float* Wv       = (const float*)d_in[9];
    const float* Wo       = (const float*)d_in[10];
    const float* means    = (const float*)d_in[11];
    const float* ln2_g    = (const float*)d_in[12];
    const float* ln2_b    = (const float*)d_in[13];
    const float* W1       = (const float*)d_in[14];
    const float* b1       = (const float*)d_in[15];
    const float* W2       = (const float*)d_in[16];
    const float* b2       = (const float*)d_in[17];
    const float* lnf_g    = (const float*)d_in[18];
    const float* lnf_b    = (const float*)d_in[19];
    const float* W_mean   = (const float*)d_in[20];
    const float* b_mean   = (const float*)d_in[21];
    const float* W_std    = (const float*)d_in[22];
    const float* b_std    = (const float*)d_in[23];

    void *ph, *pln, *pq, *pk, *pv, *pattn, *pffn, *pscores, *pcnt, *piq, *pik;
    cudaGetSymbolAddress(&ph, g_h);
    cudaGetSymbolAddress(&pln, g_ln);
    cudaGetSymbolAddress(&pq, g_q);
    cudaGetSymbolAddress(&pk, g_k);
    cudaGetSymbolAddress(&pv, g_v);
    cudaGetSymbolAddress(&pattn, g_attn);
    cudaGetSymbolAddress(&pffn, g_ffn);
    cudaGetSymbolAddress(&pscores, g_scores);
    cudaGetSymbolAddress(&pcnt, g_cnt);
    cudaGetSymbolAddress(&piq, g_iq);
    cudaGetSymbolAddress(&pik, g_ik);
    float* h    = (float*)ph;
    float* ln   = (float*)pln;
    float* q    = (float*)pq;
    float* k    = (float*)pk;
    float* v    = (float*)pv;
    float* attn = (float*)pattn;
    float* ffn  = (float*)pffn;
    float* scr  = (float*)pscores;
    float* cnt  = (float*)pcnt;
    int*   iq   = (int*)piq;
    int*   ik   = (int*)pik;

    const int attn_smem = 2 * kW * kDH * (int)sizeof(float);  // 64 KB
    cudaFuncSetAttribute(attn_kernel, cudaFuncAttributeMaxDynamicSharedMemorySize, attn_smem);

    // embedding
    {
        int total = kB * kS * kD;
        embed_kernel<<<(total + 255) / 256, 256>>>(past_x, past_y, future_x, W_emb, b_emb, h);
    }

    for (int l = 0; l < kL; l++) {
        const float* mns = means + (size_t)l * kH * kC * kDH;
        // --- attention block ---
        ln_kernel<<<kM, 128>>>(h, ln, ln1_g + (size_t)l * kD, ln1_b + (size_t)l * kD);
        launch_gemm(ln, Wq + (size_t)l * kD * kD, nullptr, nullptr, q, kM, kD, kD, 0);
        launch_gemm(ln, Wk + (size_t)l * kD * kD, nullptr, nullptr, k, kM, kD, kD, 0);
        launch_gemm(ln, Wv + (size_t)l * kD * kD, nullptr, nullptr, v, kM, kD, kD, 0);

        score_kernel<<<kM, 256>>>(q, mns, scr);
        topk_kernel<<<kB * kH * kC, 1024>>>(scr, iq);
        score_kernel<<<kM, 256>>>(k, mns, scr);
        topk_kernel<<<kB * kH * kC, 1024>>>(scr, ik);

        cudaMemsetAsync(attn, 0, (size_t)kB * kS * kD * sizeof(float), 0);
        cudaMemsetAsync(cnt, 0, (size_t)kB * kH * kS * sizeof(float), 0);
        attn_kernel<<<kB * kH * kC, 128, attn_smem>>>(q, k, v, iq, ik, attn, cnt);
        {
            int total = kB * kS * kD;
            divcnt_kernel<<<(total + 255) / 256, 256>>>(attn, cnt);
        }
        // h = h + attn @ Wo
        launch_gemm(attn, Wo + (size_t)l * kD * kD, nullptr, h, h, kM, kD, kD, 0);

        // --- FFN block ---
        ln_kernel<<<kM, 128>>>(h, ln, ln2_g + (size_t)l * kD, ln2_b + (size_t)l * kD);
        launch_gemm(ln, W1 + (size_t)l * kD * kFF, b1 + (size_t)l * kFF, nullptr, ffn, kM, kFF, kD, 1);
        launch_gemm(ffn, W2 + (size_t)l * kFF * kD, b2 + (size_t)l * kD, h, h, kM, kD, kFF, 0);
    }

    // final LN + heads
    ln_kernel<<<kM, 128>>>(h, ln, lnf_g, lnf_b);
    {
        int warps = kB * kSF;
        int threads = warps * 32;
        head_kernel<<<(threads + 255) / 256, 256>>>(ln, W_mean, b_mean, W_std, b_std, (float*)d_out);
    }
}